// round 11
// baseline (speedup 1.0000x reference)
#include <cuda_runtime.h>

// DifferentiableTTFSEncoder: first-fire one-hot over T=64 steps.
// out[b, t, n] = 1.0f at the first t where the exact-fp32 LIF recurrence
// mem = fmaf(mem, d, c*(1-d)), c = x[b,n]*sens[n], crosses 1.0; else 0.
//
// Store-wall kernel: 512 MB write-once output; measured wall ~6.0 TB/s.
// Winning config (R10): interleaved one-STG.128.CS-per-step, natural regs.
// R11: final probe — block=512 (grid=1024), same code/pacing, fewer block
// boundaries in the L1tex store queue. Everything else byte-identical.

#define B_DIM 2048
#define N_DIM 1024
#define T_DIM 64
#define NQ    (N_DIM / 4)   // float4 groups per row = 256

__global__ void __launch_bounds__(512)
ttfs_kernel(const float* __restrict__ x,
            const float* __restrict__ sens,
            float* __restrict__ out)
{
    const int gid = blockIdx.x * blockDim.x + threadIdx.x;  // over B*N/4
    const int b  = gid >> 8;        // / NQ (NQ = 256)
    const int nq = gid & (NQ - 1);  // % NQ

    // Inputs (coalesced float4)
    const float4 xv = reinterpret_cast<const float4*>(x)[gid];
    const float4 sv = reinterpret_cast<const float4*>(sens)[nq];

    const float d   = 0.60653065971263342360f;  // exp(-0.5), fp32-rounded
    const float omd = 1.0f - d;

    // Per-element constant drive c*(1-d)
    const float cc0 = xv.x * sv.x * omd;
    const float cc1 = xv.y * sv.y * omd;
    const float cc2 = xv.z * sv.z * omd;
    const float cc3 = xv.w * sv.w * omd;

    float m0 = 0.0f, m1 = 0.0f, m2 = 0.0f, m3 = 0.0f;
    bool  f0 = false, f1 = false, f2 = false, f3 = false;

    // Output base: out[b, t, n] with n = nq*4; stride per t is N_DIM floats
    float4* op = reinterpret_cast<float4*>(out)
               + (size_t)b * (size_t)T_DIM * NQ + nq;

    #pragma unroll
    for (int t = 0; t < T_DIM; ++t) {
        m0 = fmaf(m0, d, cc0);
        m1 = fmaf(m1, d, cc1);
        m2 = fmaf(m2, d, cc2);
        m3 = fmaf(m3, d, cc3);

        const bool s0 = (m0 >= 1.0f);
        const bool s1 = (m1 >= 1.0f);
        const bool s2 = (m2 >= 1.0f);
        const bool s3 = (m3 >= 1.0f);

        float4 v;
        v.x = (s0 && !f0) ? 1.0f : 0.0f;
        v.y = (s1 && !f1) ? 1.0f : 0.0f;
        v.z = (s2 && !f2) ? 1.0f : 0.0f;
        v.w = (s3 && !f3) ? 1.0f : 0.0f;

        f0 = f0 || s0;
        f1 = f1 || s1;
        f2 = f2 || s2;
        f3 = f3 || s3;

        // Evict-first streaming store, one per step (measured-optimal).
        __stcs(op + (size_t)t * NQ, v);
    }
}

extern "C" void kernel_launch(void* const* d_in, const int* in_sizes, int n_in,
                              void* d_out, int out_size)
{
    const float* x    = (const float*)d_in[0];   // [2048, 1024] f32
    const float* sens = (const float*)d_in[1];   // [1024] f32
    float* out        = (float*)d_out;           // [2048, 64, 1024] f32

    const int total_threads = (B_DIM * N_DIM) / 4;  // 524288
    const int block = 512;
    const int grid  = total_threads / block;        // 1024

    ttfs_kernel<<<grid, block>>>(x, sens, out);
}

// round 12
// speedup vs baseline: 1.0085x; 1.0085x over previous
#include <cuda_runtime.h>

// DifferentiableTTFSEncoder: first-fire one-hot over T=64 steps.
// out[b, t, n] = 1.0f at the first t where the exact-fp32 LIF recurrence
// mem = fmaf(mem, d, c*(1-d)), c = x[b,n]*sens[n], crosses 1.0; else 0.
//
// CONVERGED KERNEL (R10 config, measured optimum at 79.5us / 6.02 TB/s).
// 512 MB write-once output against the GB300 DRAM pure-write wall
// (~75% of 8 TB/s aggregate spec). 11 rounds of experiments established:
//  - interleaved one-STG.128-per-step is the optimal drain pattern
//    (bursting, decoupling, wider stores all back up L1tex and regress);
//  - .cs evict-first policy is worth ~2-3%; .wt is not;
//  - occupancy 6-8 blocks/SM, wave shape, and block size are non-levers;
//  - natural register allocation (regs=34) beats forced regs<=32.

#define B_DIM 2048
#define N_DIM 1024
#define T_DIM 64
#define NQ    (N_DIM / 4)   // float4 groups per row = 256

__global__ void __launch_bounds__(256)
ttfs_kernel(const float* __restrict__ x,
            const float* __restrict__ sens,
            float* __restrict__ out)
{
    const int gid = blockIdx.x * blockDim.x + threadIdx.x;  // over B*N/4
    const int b  = gid >> 8;        // / NQ (NQ = 256)
    const int nq = gid & (NQ - 1);  // % NQ

    // Inputs (coalesced float4)
    const float4 xv = reinterpret_cast<const float4*>(x)[gid];
    const float4 sv = reinterpret_cast<const float4*>(sens)[nq];

    const float d   = 0.60653065971263342360f;  // exp(-0.5), fp32-rounded
    const float omd = 1.0f - d;

    // Per-element constant drive c*(1-d)
    const float cc0 = xv.x * sv.x * omd;
    const float cc1 = xv.y * sv.y * omd;
    const float cc2 = xv.z * sv.z * omd;
    const float cc3 = xv.w * sv.w * omd;

    float m0 = 0.0f, m1 = 0.0f, m2 = 0.0f, m3 = 0.0f;
    bool  f0 = false, f1 = false, f2 = false, f3 = false;

    // Output base: out[b, t, n] with n = nq*4; stride per t is N_DIM floats
    float4* op = reinterpret_cast<float4*>(out)
               + (size_t)b * (size_t)T_DIM * NQ + nq;

    #pragma unroll
    for (int t = 0; t < T_DIM; ++t) {
        m0 = fmaf(m0, d, cc0);
        m1 = fmaf(m1, d, cc1);
        m2 = fmaf(m2, d, cc2);
        m3 = fmaf(m3, d, cc3);

        const bool s0 = (m0 >= 1.0f);
        const bool s1 = (m1 >= 1.0f);
        const bool s2 = (m2 >= 1.0f);
        const bool s3 = (m3 >= 1.0f);

        float4 v;
        v.x = (s0 && !f0) ? 1.0f : 0.0f;
        v.y = (s1 && !f1) ? 1.0f : 0.0f;
        v.z = (s2 && !f2) ? 1.0f : 0.0f;
        v.w = (s3 && !f3) ? 1.0f : 0.0f;

        f0 = f0 || s0;
        f1 = f1 || s1;
        f2 = f2 || s2;
        f3 = f3 || s3;

        // Evict-first streaming store (STG.E.128.CS), one per step —
        // the measured-optimal interleaved drain pattern.
        __stcs(op + (size_t)t * NQ, v);
    }
}

extern "C" void kernel_launch(void* const* d_in, const int* in_sizes, int n_in,
                              void* d_out, int out_size)
{
    const float* x    = (const float*)d_in[0];   // [2048, 1024] f32
    const float* sens = (const float*)d_in[1];   // [1024] f32
    float* out        = (float*)d_out;           // [2048, 64, 1024] f32

    const int total_threads = (B_DIM * N_DIM) / 4;  // 524288
    const int block = 256;
    const int grid  = total_threads / block;        // 2048

    ttfs_kernel<<<grid, block>>>(x, sens, out);
}